// round 1
// baseline (speedup 1.0000x reference)
#include <cuda_runtime.h>
#include <math.h>

// Problem constants
#define BB 4
#define CC 512
#define HH 128
#define WW 128
#define NN (HH*WW)          // 16384
#define CQ 64
#define OQK 128             // fused q(64) + k(64)

// ---------------- scratch (device globals; no allocation allowed) -----------
__device__ float g_qk[(size_t)BB*NN*OQK];       //  qk_t[b][n][0..63]=q, [64..127]=k
__device__ float g_v [(size_t)BB*NN*CC];        //  v_t[b][n][c]
__device__ float g_eH[(size_t)BB*HH*WW*HH];     //  eH[b][h][w][i]
__device__ float g_eW[(size_t)BB*HH*WW*WW];     //  eW[b][h][w][j]
__device__ float g_oH[(size_t)BB*NN*CC];        //  oH[((b*W+w)*H+h)*C + c]
__device__ float g_oW[(size_t)BB*NN*CC];        //  oW[((b*H+h)*W+w)*C + c]
__device__ float g_Wqk[OQK*CC];
__device__ float g_bqk[OQK];

// ---------------- pack Wq,Wk -> combined ------------------------------------
__global__ void pack_wqk(const float* __restrict__ Wq, const float* __restrict__ bq,
                         const float* __restrict__ Wk, const float* __restrict__ bk)
{
    int i = blockIdx.x * blockDim.x + threadIdx.x;
    if (i < CQ*CC) {
        g_Wqk[i]          = Wq[i];
        g_Wqk[CQ*CC + i]  = Wk[i];
    }
    if (i < CQ) { g_bqk[i] = bq[i]; g_bqk[CQ + i] = bk[i]; }
}

// ---------------- GEMM: out_t[b][n][o] = sum_c W[o][c]*X[b][c][n] + bias[o] --
// mode 0: W=g_Wqk, bias=g_bqk, out=g_qk, O=128
// mode 1: W=Wp,    bias=bp,    out=g_v,  O=512
__global__ __launch_bounds__(256)
void gemm_xw_t(const float* __restrict__ X, const float* __restrict__ Wp,
               const float* __restrict__ bp, int mode)
{
    const int O = mode ? CC : OQK;
    const float* Wm   = mode ? Wp : g_Wqk;
    const float* bias = mode ? bp : g_bqk;
    float* outp       = mode ? g_v : g_qk;

    int b  = blockIdx.z;
    int n0 = blockIdx.x * 128;
    int o0 = blockIdx.y * 128;

    __shared__ float Xs[16][128];
    __shared__ float Ws[16][129];

    int tid = threadIdx.x;
    int tx = tid & 15, ty = tid >> 4;

    float acc[8][8];
    #pragma unroll
    for (int i = 0; i < 8; i++)
        #pragma unroll
        for (int j = 0; j < 8; j++) acc[i][j] = 0.f;

    const float* Xp = X + (size_t)b * CC * NN + n0;   // + c*NN + n
    const float* Wb = Wm + (size_t)o0 * CC;           // + o*CC + c

    for (int c0 = 0; c0 < CC; c0 += 16) {
        #pragma unroll
        for (int r = 0; r < 8; r++) {
            int e = tid + r * 256;
            int kk = e >> 7, n = e & 127;
            Xs[kk][n] = Xp[(size_t)(c0 + kk) * NN + n];
        }
        #pragma unroll
        for (int r = 0; r < 8; r++) {
            int e = tid + r * 256;
            int kk = e & 15, o = e >> 4;
            Ws[kk][o] = Wb[(size_t)o * CC + c0 + kk];
        }
        __syncthreads();
        #pragma unroll
        for (int kk = 0; kk < 16; kk++) {
            float a[8], w[8];
            #pragma unroll
            for (int i = 0; i < 8; i++) a[i] = Xs[kk][ty + 16*i];
            #pragma unroll
            for (int j = 0; j < 8; j++) w[j] = Ws[kk][tx + 16*j];
            #pragma unroll
            for (int i = 0; i < 8; i++)
                #pragma unroll
                for (int j = 0; j < 8; j++) acc[i][j] += a[i] * w[j];
        }
        __syncthreads();
    }

    #pragma unroll
    for (int i = 0; i < 8; i++) {
        int n = n0 + ty + 16*i;
        size_t row = ((size_t)b * NN + n) * O + o0;
        #pragma unroll
        for (int j = 0; j < 8; j++) {
            int o = o0 + tx + 16*j;
            outp[row + tx + 16*j] = acc[i][j] + bias[o];
        }
    }
}

// ---------------- energy: E[r][s] = dot64(q_row[r], k_row[s]) ---------------
// isH=1: fixed w=f, rows are h (stride W*128 in qk), out eH[b][h][w][i], mask r==s
// isH=0: fixed h=f, rows are w (stride 128),        out eW[b][h][w][j]
__global__ __launch_bounds__(256)
void energy_kernel(int isH)
{
    int b = blockIdx.z, f = blockIdx.x;
    int r0 = (blockIdx.y >> 1) * 64;
    int s0 = (blockIdx.y & 1) * 64;

    size_t qbase; size_t obase; int rq; int ro;
    if (isH) { qbase = ((size_t)b*NN + f) * OQK;            rq = WW*OQK;
               obase = (size_t)b*HH*WW*HH + (size_t)f*HH;   ro = WW*HH; }
    else     { qbase = ((size_t)b*NN + (size_t)f*WW) * OQK; rq = OQK;
               obase = (size_t)b*HH*WW*WW + (size_t)f*WW*WW; ro = WW; }
    float* outp = isH ? g_eH : g_eW;

    __shared__ float As[64][65];
    __shared__ float Bs[64][65];

    int tid = threadIdx.x;
    int tx = tid & 15, ty = tid >> 4;

    #pragma unroll
    for (int r = 0; r < 16; r++) {
        int e = tid + r * 256;
        int row = e >> 6, c = e & 63;
        As[row][c] = g_qk[qbase + (size_t)(r0 + row) * rq + c];
        Bs[row][c] = g_qk[qbase + (size_t)(s0 + row) * rq + 64 + c];
    }
    __syncthreads();

    float acc[4][4];
    #pragma unroll
    for (int i = 0; i < 4; i++)
        #pragma unroll
        for (int j = 0; j < 4; j++) acc[i][j] = 0.f;

    #pragma unroll
    for (int c = 0; c < 64; c++) {
        float a[4], bb[4];
        #pragma unroll
        for (int i = 0; i < 4; i++) a[i] = As[ty + 16*i][c];
        #pragma unroll
        for (int j = 0; j < 4; j++) bb[j] = Bs[tx + 16*j][c];
        #pragma unroll
        for (int i = 0; i < 4; i++)
            #pragma unroll
            for (int j = 0; j < 4; j++) acc[i][j] += a[i] * bb[j];
    }

    #pragma unroll
    for (int i = 0; i < 4; i++) {
        int r = r0 + ty + 16*i;
        #pragma unroll
        for (int j = 0; j < 4; j++) {
            int s = s0 + tx + 16*j;
            float val = acc[i][j];
            if (isH && r == s) val = -INFINITY;
            outp[obase + (size_t)r * ro + s] = val;
        }
    }
}

// ---------------- softmax over concat(eH[128], eW[128]) per (b,h,w) ---------
__global__ void softmax_kernel()
{
    int gwarp = (blockIdx.x * blockDim.x + threadIdx.x) >> 5;
    int lane  = threadIdx.x & 31;
    if (gwarp >= BB*HH*WW) return;

    float4* pH = (float4*)(g_eH + (size_t)gwarp * HH);
    float4* pW = (float4*)(g_eW + (size_t)gwarp * WW);
    float4 vH = pH[lane];
    float4 vW = pW[lane];

    float m = fmaxf(fmaxf(fmaxf(vH.x, vH.y), fmaxf(vH.z, vH.w)),
                    fmaxf(fmaxf(vW.x, vW.y), fmaxf(vW.z, vW.w)));
    #pragma unroll
    for (int off = 16; off; off >>= 1)
        m = fmaxf(m, __shfl_xor_sync(0xffffffffu, m, off));

    vH.x = __expf(vH.x - m); vH.y = __expf(vH.y - m);
    vH.z = __expf(vH.z - m); vH.w = __expf(vH.w - m);
    vW.x = __expf(vW.x - m); vW.y = __expf(vW.y - m);
    vW.z = __expf(vW.z - m); vW.w = __expf(vW.w - m);

    float s = vH.x + vH.y + vH.z + vH.w + vW.x + vW.y + vW.z + vW.w;
    #pragma unroll
    for (int off = 16; off; off >>= 1)
        s += __shfl_xor_sync(0xffffffffu, s, off);
    float inv = 1.f / s;

    vH.x *= inv; vH.y *= inv; vH.z *= inv; vH.w *= inv;
    vW.x *= inv; vW.y *= inv; vW.z *= inv; vW.w *= inv;
    pH[lane] = vH;
    pW[lane] = vW;
}

// ---------------- out GEMM: Out[n][c] = sum_k V[c][k] * A[n][k] -------------
// isH=1 (f=w): V[c][i]=v_t[(b*N+i*W+f)*C+c], A[h][i]=eH, out g_oH
// isH=0 (f=h): V[c][j]=v_t[(b*N+f*W+j)*C+c], A[w][j]=eW, out g_oW
__global__ __launch_bounds__(256)
void out_gemm(int isH)
{
    int bz = blockIdx.z;
    int b = bz >> 7, f = bz & 127;
    int c0 = blockIdx.x * 128;

    size_t vbase; size_t kstride; size_t abase; int anstride;
    if (isH) { vbase = ((size_t)b*NN + f) * CC;             kstride = (size_t)WW*CC;
               abase = (size_t)b*HH*WW*HH + (size_t)f*HH;   anstride = WW*HH; }
    else     { vbase = ((size_t)b*NN + (size_t)f*WW) * CC;  kstride = CC;
               abase = (size_t)b*HH*WW*WW + (size_t)f*WW*WW; anstride = WW; }
    const float* attn = isH ? g_eH : g_eW;
    float* outp       = isH ? g_oH : g_oW;
    size_t obase = ((size_t)b*128 + f) * 128 * CC;

    __shared__ float Vs[16][128];
    __shared__ float As_[128][17];

    int tid = threadIdx.x;
    int tx = tid & 15, ty = tid >> 4;

    float acc[8][8];
    #pragma unroll
    for (int i = 0; i < 8; i++)
        #pragma unroll
        for (int j = 0; j < 8; j++) acc[i][j] = 0.f;

    for (int k0 = 0; k0 < 128; k0 += 16) {
        #pragma unroll
        for (int r = 0; r < 8; r++) {
            int e = tid + r * 256;
            int kk = e >> 7, c = e & 127;
            Vs[kk][c] = g_v[vbase + (size_t)(k0 + kk) * kstride + c0 + c];
        }
        #pragma unroll
        for (int r = 0; r < 8; r++) {
            int e = tid + r * 256;
            int i = e & 15, n = e >> 4;
            As_[n][i] = attn[abase + (size_t)n * anstride + k0 + i];
        }
        __syncthreads();
        #pragma unroll
        for (int kk = 0; kk < 16; kk++) {
            float a[8], vv[8];
            #pragma unroll
            for (int i = 0; i < 8; i++) a[i]  = As_[ty + 16*i][kk];
            #pragma unroll
            for (int j = 0; j < 8; j++) vv[j] = Vs[kk][tx + 16*j];
            #pragma unroll
            for (int i = 0; i < 8; i++)
                #pragma unroll
                for (int j = 0; j < 8; j++) acc[i][j] += a[i] * vv[j];
        }
        __syncthreads();
    }

    #pragma unroll
    for (int i = 0; i < 8; i++) {
        size_t row = obase + (size_t)(ty + 16*i) * CC + c0;
        #pragma unroll
        for (int j = 0; j < 8; j++)
            outp[row + tx + 16*j] = acc[i][j];
    }
}

// ---------------- combine: out = gamma*(oH + oW) + x (layout flip) ----------
__global__ void combine_kernel(const float* __restrict__ x,
                               const float* __restrict__ gamma,
                               float* __restrict__ out)
{
    int b = blockIdx.z >> 7;
    int h = blockIdx.z & 127;
    int w0 = blockIdx.x * 32;
    int c0 = blockIdx.y * 32;

    __shared__ float s[32][33];
    int tx = threadIdx.x, ty = threadIdx.y;

    // read with c contiguous: (w=w0+ty, c=c0+tx)
    float vW = g_oW[(((size_t)b*HH + h) * WW + (w0 + ty)) * CC + c0 + tx];
    float vH = g_oH[(((size_t)b*WW + (w0 + ty)) * HH + h) * CC + c0 + tx];
    s[ty][tx] = vW + vH;
    __syncthreads();

    // write with w contiguous: (c=c0+ty, w=w0+tx)
    size_t oidx = (((size_t)b*CC + c0 + ty) * HH + h) * WW + w0 + tx;
    out[oidx] = gamma[0] * s[tx][ty] + x[oidx];
}

// ---------------- launch -----------------------------------------------------
extern "C" void kernel_launch(void* const* d_in, const int* in_sizes, int n_in,
                              void* d_out, int out_size)
{
    const float* x     = (const float*)d_in[0];
    const float* Wq    = (const float*)d_in[1];
    const float* bq    = (const float*)d_in[2];
    const float* Wk    = (const float*)d_in[3];
    const float* bk    = (const float*)d_in[4];
    const float* Wv    = (const float*)d_in[5];
    const float* bv    = (const float*)d_in[6];
    const float* gamma = (const float*)d_in[7];
    float* out = (float*)d_out;

    // 0) pack q/k weights
    pack_wqk<<<128, 256>>>(Wq, bq, Wk, bk);

    // 1) qk = [Wq;Wk] @ x  -> g_qk[b][n][128]
    gemm_xw_t<<<dim3(NN/128, OQK/128, BB), 256>>>(x, nullptr, nullptr, 0);
    // 2) v = Wv @ x        -> g_v[b][n][512]
    gemm_xw_t<<<dim3(NN/128, CC/128, BB), 256>>>(x, Wv, bv, 1);

    // 3) energies
    energy_kernel<<<dim3(WW, 4, BB), 256>>>(1);   // eH
    energy_kernel<<<dim3(HH, 4, BB), 256>>>(0);   // eW

    // 4) softmax over concat
    softmax_kernel<<<(BB*HH*WW*32 + 255) / 256, 256>>>();

    // 5) output GEMMs
    out_gemm<<<dim3(CC/128, 1, BB*WW), 256>>>(1); // oH
    out_gemm<<<dim3(CC/128, 1, BB*HH), 256>>>(0); // oW

    // 6) combine + residual
    combine_kernel<<<dim3(WW/32, CC/32, BB*HH), dim3(32, 32)>>>(x, gamma, out);
}

// round 2
// speedup vs baseline: 2.3165x; 2.3165x over previous
#include <cuda_runtime.h>
#include <math.h>
#include <stdint.h>

// Problem constants
#define BB 4
#define CC 512
#define HH 128
#define WW 128
#define NN (HH*WW)          // 16384
#define CQ 64
#define OQK 128             // fused q(64) + k(64)

// ---------------- scratch (device globals; no allocation allowed) -----------
__device__ float g_qk[(size_t)BB*NN*OQK];       //  qk_t[b][n][0..63]=q, [64..127]=k
__device__ float g_v [(size_t)BB*NN*CC];        //  v_t[b][n][c]
__device__ float g_eH[(size_t)BB*HH*WW*HH];     //  eH[b][h][w][i]
__device__ float g_eW[(size_t)BB*HH*WW*WW];     //  eW[b][h][w][j]
__device__ float g_oH[(size_t)BB*NN*CC];        //  oH[((b*W+w)*H+h)*C + c]
__device__ float g_oW[(size_t)BB*NN*CC];        //  oW[((b*H+h)*W+w)*C + c]
__device__ float g_Wqk[OQK*CC];
__device__ float g_bqk[OQK];

// ---------------- tf32 mma helpers ------------------------------------------
__device__ __forceinline__ uint32_t f2tf(float f) {
    uint32_t u;
    asm("cvt.rna.tf32.f32 %0, %1;" : "=r"(u) : "f"(f));
    return u;
}

__device__ __forceinline__ void mma_tf32(float c[4], const uint32_t a[4], const uint32_t b[2]) {
    asm volatile(
        "mma.sync.aligned.m16n8k8.row.col.f32.tf32.tf32.f32 "
        "{%0,%1,%2,%3}, {%4,%5,%6,%7}, {%8,%9}, {%0,%1,%2,%3};"
        : "+f"(c[0]), "+f"(c[1]), "+f"(c[2]), "+f"(c[3])
        : "r"(a[0]), "r"(a[1]), "r"(a[2]), "r"(a[3]), "r"(b[0]), "r"(b[1]));
}

// ---------------- pack Wq,Wk -> combined ------------------------------------
__global__ void pack_wqk(const float* __restrict__ Wq, const float* __restrict__ bq,
                         const float* __restrict__ Wk, const float* __restrict__ bk)
{
    int i = blockIdx.x * blockDim.x + threadIdx.x;
    if (i < CQ*CC) {
        g_Wqk[i]          = Wq[i];
        g_Wqk[CQ*CC + i]  = Wk[i];
    }
    if (i < CQ) { g_bqk[i] = bq[i]; g_bqk[CQ + i] = bk[i]; }
}

// ---------------- TC GEMM: out_t[b][n][o] = sum_c W[o][c]*X[b][c][n] + bias[o]
// mode 0: W=g_Wqk, bias=g_bqk, out=g_qk, O=128
// mode 1: W=Wp,    bias=bp,    out=g_v,  O=512
// Block tile 128(n) x 128(o), K-tile 32, 8 warps (2x4), warp tile 64x32.
__global__ __launch_bounds__(256)
void gemm_qkv_tc(const float* __restrict__ X, const float* __restrict__ Wp,
                 const float* __restrict__ bp, int mode)
{
    const int O = mode ? CC : OQK;
    const float* Wm   = mode ? Wp : g_Wqk;
    const float* bias = mode ? bp : g_bqk;
    float* outp       = mode ? g_v : g_qk;

    const int b  = blockIdx.z;
    const int n0 = blockIdx.x * 128;
    const int o0 = blockIdx.y * 128;

    __shared__ uint32_t As[32][136];   // [k][m] pad->(8*tig+g)%32 conflict-free
    __shared__ uint32_t Bs[128][36];   // [o][k] pad->(4*g+tig)%32 conflict-free

    const int tid  = threadIdx.x;
    const int warp = tid >> 5;
    const int lane = tid & 31;
    const int g    = lane >> 2;        // groupID
    const int tig  = lane & 3;         // thread in group
    const int wm   = warp >> 2;        // 0..1
    const int wn   = warp & 3;         // 0..3

    float acc[4][4][4];
    #pragma unroll
    for (int i = 0; i < 4; i++)
        #pragma unroll
        for (int j = 0; j < 4; j++)
            #pragma unroll
            for (int r = 0; r < 4; r++) acc[i][j][r] = 0.f;

    const float* Xp = X + (size_t)b * CC * NN + n0;   // + c*NN + m
    const float* Wb = Wm + (size_t)o0 * CC;           // + o*CC + c

    const int col4  = tid & 31;        // A-load: float4 index along m
    const int krowA = tid >> 5;        // A-load: k row (0..7, +8 per iter)
    const int orow  = tid >> 1;        // B-load: o row
    const int kcB   = (tid & 1) * 16;  // B-load: k chunk

    for (int c0 = 0; c0 < CC; c0 += 32) {
        // As[k][m] <- X[c0+k][n0+m]
        #pragma unroll
        for (int it = 0; it < 4; it++) {
            int kk = krowA + it * 8;
            float4 v = *(const float4*)(Xp + (size_t)(c0 + kk) * NN + col4 * 4);
            uint32_t* dst = &As[kk][col4 * 4];
            dst[0] = f2tf(v.x); dst[1] = f2tf(v.y); dst[2] = f2tf(v.z); dst[3] = f2tf(v.w);
        }
        // Bs[o][k] <- W[o0+o][c0+k]
        #pragma unroll
        for (int it = 0; it < 4; it++) {
            float4 v = *(const float4*)(Wb + (size_t)orow * CC + c0 + kcB + it * 4);
            uint32_t* dst = &Bs[orow][kcB + it * 4];
            dst[0] = f2tf(v.x); dst[1] = f2tf(v.y); dst[2] = f2tf(v.z); dst[3] = f2tf(v.w);
        }
        __syncthreads();

        #pragma unroll
        for (int k8 = 0; k8 < 32; k8 += 8) {
            uint32_t af[4][4], bf[4][2];
            #pragma unroll
            for (int mt = 0; mt < 4; mt++) {
                int rb = wm * 64 + mt * 16;
                af[mt][0] = As[k8 + tig    ][rb + g    ];
                af[mt][1] = As[k8 + tig    ][rb + g + 8];
                af[mt][2] = As[k8 + tig + 4][rb + g    ];
                af[mt][3] = As[k8 + tig + 4][rb + g + 8];
            }
            #pragma unroll
            for (int nt = 0; nt < 4; nt++) {
                int cb = wn * 32 + nt * 8 + g;
                bf[nt][0] = Bs[cb][k8 + tig    ];
                bf[nt][1] = Bs[cb][k8 + tig + 4];
            }
            #pragma unroll
            for (int mt = 0; mt < 4; mt++)
                #pragma unroll
                for (int nt = 0; nt < 4; nt++)
                    mma_tf32(acc[mt][nt], af[mt], bf[nt]);
        }
        __syncthreads();
    }

    // epilogue: out[(b*NN + n)*O + o] + bias
    #pragma unroll
    for (int mt = 0; mt < 4; mt++) {
        int row = n0 + wm * 64 + mt * 16 + g;
        #pragma unroll
        for (int nt = 0; nt < 4; nt++) {
            int col = o0 + wn * 32 + nt * 8 + tig * 2;
            float b0 = bias[col], b1 = bias[col + 1];
            size_t base0 = ((size_t)b * NN + row) * O + col;
            size_t base1 = base0 + (size_t)8 * O;
            *(float2*)(outp + base0) = make_float2(acc[mt][nt][0] + b0, acc[mt][nt][1] + b1);
            *(float2*)(outp + base1) = make_float2(acc[mt][nt][2] + b0, acc[mt][nt][3] + b1);
        }
    }
}

// ---------------- energy: E[r][s] = dot64(q_row[r], k_row[s]) ---------------
__global__ __launch_bounds__(256)
void energy_kernel(int isH)
{
    int b = blockIdx.z, f = blockIdx.x;
    int r0 = (blockIdx.y >> 1) * 64;
    int s0 = (blockIdx.y & 1) * 64;

    size_t qbase; size_t obase; int rq; int ro;
    if (isH) { qbase = ((size_t)b*NN + f) * OQK;            rq = WW*OQK;
               obase = (size_t)b*HH*WW*HH + (size_t)f*HH;   ro = WW*HH; }
    else     { qbase = ((size_t)b*NN + (size_t)f*WW) * OQK; rq = OQK;
               obase = (size_t)b*HH*WW*WW + (size_t)f*WW*WW; ro = WW; }
    float* outp = isH ? g_eH : g_eW;

    __shared__ float As[64][65];
    __shared__ float Bs[64][65];

    int tid = threadIdx.x;
    int tx = tid & 15, ty = tid >> 4;

    #pragma unroll
    for (int r = 0; r < 16; r++) {
        int e = tid + r * 256;
        int row = e >> 6, c = e & 63;
        As[row][c] = g_qk[qbase + (size_t)(r0 + row) * rq + c];
        Bs[row][c] = g_qk[qbase + (size_t)(s0 + row) * rq + 64 + c];
    }
    __syncthreads();

    float acc[4][4];
    #pragma unroll
    for (int i = 0; i < 4; i++)
        #pragma unroll
        for (int j = 0; j < 4; j++) acc[i][j] = 0.f;

    #pragma unroll
    for (int c = 0; c < 64; c++) {
        float a[4], bb[4];
        #pragma unroll
        for (int i = 0; i < 4; i++) a[i] = As[ty + 16*i][c];
        #pragma unroll
        for (int j = 0; j < 4; j++) bb[j] = Bs[tx + 16*j][c];
        #pragma unroll
        for (int i = 0; i < 4; i++)
            #pragma unroll
            for (int j = 0; j < 4; j++) acc[i][j] += a[i] * bb[j];
    }

    #pragma unroll
    for (int i = 0; i < 4; i++) {
        int r = r0 + ty + 16*i;
        #pragma unroll
        for (int j = 0; j < 4; j++) {
            int s = s0 + tx + 16*j;
            float val = acc[i][j];
            if (isH && r == s) val = -INFINITY;
            outp[obase + (size_t)r * ro + s] = val;
        }
    }
}

// ---------------- softmax over concat(eH[128], eW[128]) per (b,h,w) ---------
__global__ void softmax_kernel()
{
    int gwarp = (blockIdx.x * blockDim.x + threadIdx.x) >> 5;
    int lane  = threadIdx.x & 31;
    if (gwarp >= BB*HH*WW) return;

    float4* pH = (float4*)(g_eH + (size_t)gwarp * HH);
    float4* pW = (float4*)(g_eW + (size_t)gwarp * WW);
    float4 vH = pH[lane];
    float4 vW = pW[lane];

    float m = fmaxf(fmaxf(fmaxf(vH.x, vH.y), fmaxf(vH.z, vH.w)),
                    fmaxf(fmaxf(vW.x, vW.y), fmaxf(vW.z, vW.w)));
    #pragma unroll
    for (int off = 16; off; off >>= 1)
        m = fmaxf(m, __shfl_xor_sync(0xffffffffu, m, off));

    vH.x = __expf(vH.x - m); vH.y = __expf(vH.y - m);
    vH.z = __expf(vH.z - m); vH.w = __expf(vH.w - m);
    vW.x = __expf(vW.x - m); vW.y = __expf(vW.y - m);
    vW.z = __expf(vW.z - m); vW.w = __expf(vW.w - m);

    float s = vH.x + vH.y + vH.z + vH.w + vW.x + vW.y + vW.z + vW.w;
    #pragma unroll
    for (int off = 16; off; off >>= 1)
        s += __shfl_xor_sync(0xffffffffu, s, off);
    float inv = 1.f / s;

    vH.x *= inv; vH.y *= inv; vH.z *= inv; vH.w *= inv;
    vW.x *= inv; vW.y *= inv; vW.z *= inv; vW.w *= inv;
    pH[lane] = vH;
    pW[lane] = vW;
}

// ---------------- TC out GEMM: Out[n][c] = sum_k A[n][k] * V[k][c] ----------
// isH=1 (f=w): V[c][i]=v_t[(b*N+i*W+f)*C+c], A[h][i]=eH, out g_oH
// isH=0 (f=h): V[c][j]=v_t[(b*N+f*W+j)*C+c], A[w][j]=eW, out g_oW
// Block: 128(n) x 128(c), K-tile 32 (K=128 total), 8 warps (2x4).
__global__ __launch_bounds__(256)
void out_gemm_tc(int isH)
{
    int bz = blockIdx.z;
    int b = bz >> 7, f = bz & 127;
    int c0 = blockIdx.x * 128;

    size_t vbase; size_t kstride; size_t abase; int anstride;
    if (isH) { vbase = ((size_t)b*NN + f) * CC;             kstride = (size_t)WW*CC;
               abase = (size_t)b*HH*WW*HH + (size_t)f*HH;   anstride = WW*HH; }
    else     { vbase = ((size_t)b*NN + (size_t)f*WW) * CC;  kstride = CC;
               abase = (size_t)b*HH*WW*WW + (size_t)f*WW*WW; anstride = WW; }
    const float* attn = isH ? g_eH : g_eW;
    float* outp       = isH ? g_oH : g_oW;
    size_t obase = ((size_t)b*128 + f) * 128 * CC;

    __shared__ uint32_t As[128][36];   // [n][k]
    __shared__ uint32_t Bs[32][136];   // [k][c]

    const int tid  = threadIdx.x;
    const int warp = tid >> 5;
    const int lane = tid & 31;
    const int g    = lane >> 2;
    const int tig  = lane & 3;
    const int wm   = warp >> 2;
    const int wn   = warp & 3;

    float acc[4][4][4];
    #pragma unroll
    for (int i = 0; i < 4; i++)
        #pragma unroll
        for (int j = 0; j < 4; j++)
            #pragma unroll
            for (int r = 0; r < 4; r++) acc[i][j][r] = 0.f;

    const int nrow = tid >> 1;          // A-load
    const int kcA  = (tid & 1) * 16;
    const int krowB = tid >> 5;         // B-load
    const int col4  = tid & 31;

    for (int k0 = 0; k0 < 128; k0 += 32) {
        // As[n][k] <- attn[n][k0+k]
        #pragma unroll
        for (int it = 0; it < 4; it++) {
            float4 v = *(const float4*)(attn + abase + (size_t)nrow * anstride + k0 + kcA + it * 4);
            uint32_t* dst = &As[nrow][kcA + it * 4];
            dst[0] = f2tf(v.x); dst[1] = f2tf(v.y); dst[2] = f2tf(v.z); dst[3] = f2tf(v.w);
        }
        // Bs[k][c] <- V[k0+k][c0+c]
        #pragma unroll
        for (int it = 0; it < 4; it++) {
            int kk = krowB + it * 8;
            float4 v = *(const float4*)(g_v + vbase + (size_t)(k0 + kk) * kstride + c0 + col4 * 4);
            uint32_t* dst = &Bs[kk][col4 * 4];
            dst[0] = f2tf(v.x); dst[1] = f2tf(v.y); dst[2] = f2tf(v.z); dst[3] = f2tf(v.w);
        }
        __syncthreads();

        #pragma unroll
        for (int k8 = 0; k8 < 32; k8 += 8) {
            uint32_t af[4][4], bf[4][2];
            #pragma unroll
            for (int mt = 0; mt < 4; mt++) {
                int rb = wm * 64 + mt * 16;
                af[mt][0] = As[rb + g    ][k8 + tig    ];
                af[mt][1] = As[rb + g + 8][k8 + tig    ];
                af[mt][2] = As[rb + g    ][k8 + tig + 4];
                af[mt][3] = As[rb + g + 8][k8 + tig + 4];
            }
            #pragma unroll
            for (int nt = 0; nt < 4; nt++) {
                int cb = wn * 32 + nt * 8 + g;
                bf[nt][0] = Bs[k8 + tig    ][cb];
                bf[nt][1] = Bs[k8 + tig + 4][cb];
            }
            #pragma unroll
            for (int mt = 0; mt < 4; mt++)
                #pragma unroll
                for (int nt = 0; nt < 4; nt++)
                    mma_tf32(acc[mt][nt], af[mt], bf[nt]);
        }
        __syncthreads();
    }

    #pragma unroll
    for (int mt = 0; mt < 4; mt++) {
        int row = wm * 64 + mt * 16 + g;
        #pragma unroll
        for (int nt = 0; nt < 4; nt++) {
            int col = c0 + wn * 32 + nt * 8 + tig * 2;
            size_t base0 = obase + (size_t)row * CC + col;
            size_t base1 = base0 + (size_t)8 * CC;
            *(float2*)(outp + base0) = make_float2(acc[mt][nt][0], acc[mt][nt][1]);
            *(float2*)(outp + base1) = make_float2(acc[mt][nt][2], acc[mt][nt][3]);
        }
    }
}

// ---------------- combine: out = gamma*(oH + oW) + x (layout flip) ----------
__global__ void combine_kernel(const float* __restrict__ x,
                               const float* __restrict__ gamma,
                               float* __restrict__ out)
{
    int b = blockIdx.z >> 7;
    int h = blockIdx.z & 127;
    int w0 = blockIdx.x * 32;
    int c0 = blockIdx.y * 32;

    __shared__ float s[32][33];
    int tx = threadIdx.x, ty = threadIdx.y;

    float vW = g_oW[(((size_t)b*HH + h) * WW + (w0 + ty)) * CC + c0 + tx];
    float vH = g_oH[(((size_t)b*WW + (w0 + ty)) * HH + h) * CC + c0 + tx];
    s[ty][tx] = vW + vH;
    __syncthreads();

    size_t oidx = (((size_t)b*CC + c0 + ty) * HH + h) * WW + w0 + tx;
    out[oidx] = gamma[0] * s[tx][ty] + x[oidx];
}

// ---------------- launch -----------------------------------------------------
extern "C" void kernel_launch(void* const* d_in, const int* in_sizes, int n_in,
                              void* d_out, int out_size)
{
    const float* x     = (const float*)d_in[0];
    const float* Wq    = (const float*)d_in[1];
    const float* bq    = (const float*)d_in[2];
    const float* Wk    = (const float*)d_in[3];
    const float* bk    = (const float*)d_in[4];
    const float* Wv    = (const float*)d_in[5];
    const float* bv    = (const float*)d_in[6];
    const float* gamma = (const float*)d_in[7];
    float* out = (float*)d_out;

    // 0) pack q/k weights
    pack_wqk<<<128, 256>>>(Wq, bq, Wk, bk);

    // 1) qk = [Wq;Wk] @ x  -> g_qk[b][n][128]   (tensor core tf32)
    gemm_qkv_tc<<<dim3(NN/128, OQK/128, BB), 256>>>(x, nullptr, nullptr, 0);
    // 2) v = Wv @ x        -> g_v[b][n][512]    (tensor core tf32)
    gemm_qkv_tc<<<dim3(NN/128, CC/128, BB), 256>>>(x, Wv, bv, 1);

    // 3) energies
    energy_kernel<<<dim3(WW, 4, BB), 256>>>(1);   // eH
    energy_kernel<<<dim3(HH, 4, BB), 256>>>(0);   // eW

    // 4) softmax over concat
    softmax_kernel<<<(BB*HH*WW*32 + 255) / 256, 256>>>();

    // 5) output GEMMs (tensor core tf32)
    out_gemm_tc<<<dim3(CC/128, 1, BB*WW), 256>>>(1); // oH
    out_gemm_tc<<<dim3(CC/128, 1, BB*HH), 256>>>(0); // oW

    // 6) combine + residual
    combine_kernel<<<dim3(WW/32, CC/32, BB*HH), dim3(32, 32)>>>(x, gamma, out);
}